// round 2
// baseline (speedup 1.0000x reference)
#include <cuda_runtime.h>
#include <math.h>

#define Bv 65536
#define Tv 64
#define Uv 8

// Precomputed per-channel state (written by setup kernel, read by main kernel).
__device__ float g_w[Uv][Tv];   // flipped causal weights: w[u][s] = Kz[t_idx[u]-s, u] (0 if s > t_idx)
__device__ float g_a[Uv];       // alpha * 100
__device__ float g_b[Uv];       // beta * 10

// ---------------------------------------------------------------------------
// Setup: compute Kz, per-channel argmax -> t_idx, flipped weights. 1 block.
// ---------------------------------------------------------------------------
__global__ void setup_kernel(const float* __restrict__ alpha,
                             const float* __restrict__ beta,
                             const float* __restrict__ gammap,
                             const float* __restrict__ tauZ,
                             const float* __restrict__ nZ,
                             const float* __restrict__ tauC,
                             const float* __restrict__ nC) {
    __shared__ float Kz[Tv][Uv];
    __shared__ int   tidx[Uv];

    int tid = threadIdx.x;  // 512 threads
    if (tid < Tv * Uv) {
        int t = tid / Uv;
        int u = tid % Uv;
        float tau_c = tauC[u] * 100.0f;
        float n_c   = nC[u]   * 10.0f;
        float tau_z = tauZ[u] * 100.0f;
        float n_z   = nZ[u]   * 10.0f;
        float g     = gammap[u] * 10.0f;
        float tf = (float)t;
        // gamma_filter: t^n * exp(-t/tau) / tau^(n+1) / exp(gammaln(n+1))
        float kc = powf(tf, n_c) * expf(-tf / tau_c)
                   / powf(tau_c, n_c + 1.0f) / expf(lgammaf(n_c + 1.0f));
        float kz2 = powf(tf, n_z) * expf(-tf / tau_z)
                   / powf(tau_z, n_z + 1.0f) / expf(lgammaf(n_z + 1.0f));
        Kz[t][u] = g * kc + (1.0f - g) * kz2;
    }
    __syncthreads();

    if (tid < Uv) {
        int u = tid;
        float best = Kz[0][u];
        int bi = 0;
        for (int t = 1; t < Tv; ++t) {
            if (Kz[t][u] > best) { best = Kz[t][u]; bi = t; }  // first max wins (strict >)
        }
        int ti = Tv - bi;                 // T - z_shift
        if (ti > Tv - 1) ti = Tv - 1;
        if (ti < 0) ti = 0;
        tidx[u] = ti;
        g_a[u] = alpha[u] * 100.0f;
        g_b[u] = beta[u]  * 10.0f;
    }
    __syncthreads();

    if (tid < Tv * Uv) {
        int s = tid / Uv;
        int u = tid % Uv;
        int ti = tidx[u];
        g_w[u][s] = (s <= ti) ? Kz[ti - s][u] : 0.0f;
    }
}

// ---------------------------------------------------------------------------
// Main: one warp per batch row.
//   z_sel[u] = dot(x[b,:], w[u,:]);  scale[u] = a[u]/(1 + b[u]*z_sel[u])
//   out[b*512 + t*8 + u] = scale[u] * x[b,t]
// Stores arranged so every STG.128 across the warp is one contiguous 512B block.
// ---------------------------------------------------------------------------
__global__ __launch_bounds__(256) void main_kernel(const float* __restrict__ x,
                                                   float* __restrict__ out) {
    int warp = blockIdx.x * (blockDim.x >> 5) + (threadIdx.x >> 5);
    int lane = threadIdx.x & 31;
    if (warp >= Bv) return;

    // Load x[b, 2*lane], x[b, 2*lane+1]  (coalesced 256B per warp)
    const float2* xb = (const float2*)(x + (size_t)warp * Tv);
    float2 xv = xb[lane];

    // Partial dot products for all 8 channels
    float s[Uv];
#pragma unroll
    for (int u = 0; u < Uv; ++u) {
        const float2* wp = (const float2*)(&g_w[u][0]);
        float2 wv = wp[lane];                  // L1-resident after first warp
        s[u] = fmaf(xv.x, wv.x, xv.y * wv.y);
    }

    // Butterfly reduce each channel across the warp (all lanes end with full sum)
#pragma unroll
    for (int u = 0; u < Uv; ++u) {
#pragma unroll
        for (int off = 16; off > 0; off >>= 1)
            s[u] += __shfl_xor_sync(0xffffffffu, s[u], off);
    }

    // Per-channel scale = a / (1 + b*z)   (denom in [1,~2], fast division is plenty)
    float scale[Uv];
#pragma unroll
    for (int u = 0; u < Uv; ++u)
        scale[u] = __fdividef(g_a[u], fmaf(g_b[u], s[u], 1.0f));

    // Lane picks the 4 channels it writes: u = (lane&1)*4 + j
    bool hi = (lane & 1);
    float c0 = hi ? scale[4] : scale[0];
    float c1 = hi ? scale[5] : scale[1];
    float c2 = hi ? scale[6] : scale[2];
    float c3 = hi ? scale[7] : scale[3];

    float* ob = out + (size_t)warp * (Tv * Uv);
    int src = lane >> 2;           // partial source-lane term
    int sel = (lane >> 1) & 1;     // which component of the float2 holds x[t]

#pragma unroll
    for (int i = 0; i < 4; ++i) {
        // Element index = i*128 + lane*4 + j  ->  t = i*16 + (lane>>1)
        // x[t] lives in lane (i*8 + (lane>>2)), component (t&1) = sel
        int slane = i * 8 + src;
        float xa = __shfl_sync(0xffffffffu, xv.x, slane);
        float xb2 = __shfl_sync(0xffffffffu, xv.y, slane);
        float xt = sel ? xb2 : xa;
        float4 v = make_float4(c0 * xt, c1 * xt, c2 * xt, c3 * xt);
        // Contiguous 512B per STG across the warp
        *(float4*)(ob + i * 128 + lane * 4) = v;
    }
}

extern "C" void kernel_launch(void* const* d_in, const int* in_sizes, int n_in,
                              void* d_out, int out_size) {
    // Input order: inputs, alpha, beta, gamma, zeta, tauY, nY, tauZ, nZ, tauC, nC
    const float* inputs = (const float*)d_in[0];
    const float* alpha  = (const float*)d_in[1];
    const float* beta   = (const float*)d_in[2];
    const float* gammap = (const float*)d_in[3];
    const float* tauZ   = (const float*)d_in[7];
    const float* nZ     = (const float*)d_in[8];
    const float* tauC   = (const float*)d_in[9];
    const float* nC     = (const float*)d_in[10];
    float* out = (float*)d_out;

    setup_kernel<<<1, 512>>>(alpha, beta, gammap, tauZ, nZ, tauC, nC);

    // One warp per batch: 65536 warps = 8192 blocks x 256 threads
    main_kernel<<<Bv / 8, 256>>>(inputs, out);
}

// round 5
// speedup vs baseline: 1.0009x; 1.0009x over previous
#include <cuda_runtime.h>
#include <math.h>

#define Bv 65536
#define Tv 64
#define Uv 8

// Precomputed state (written by setup kernel, read by main kernel).
__device__ float  g_wt[Tv][Uv];   // transposed flipped weights: w_t[s][u] = Kz[t_idx[u]-s, u] (0 if s>t_idx)
__device__ float2 g_ab[Uv];       // (alpha*100, beta*10)

// ---------------------------------------------------------------------------
// Setup: compute Kz, per-channel argmax -> t_idx, flipped transposed weights.
// ---------------------------------------------------------------------------
__global__ void setup_kernel(const float* __restrict__ alpha,
                             const float* __restrict__ beta,
                             const float* __restrict__ gammap,
                             const float* __restrict__ tauZ,
                             const float* __restrict__ nZ,
                             const float* __restrict__ tauC,
                             const float* __restrict__ nC) {
    __shared__ float Kz[Tv][Uv];
    __shared__ int   tidx[Uv];

    int tid = threadIdx.x;  // 512 threads
    if (tid < Tv * Uv) {
        int t = tid / Uv;
        int u = tid % Uv;
        float tau_c = tauC[u] * 100.0f;
        float n_c   = nC[u]   * 10.0f;
        float tau_z = tauZ[u] * 100.0f;
        float n_z   = nZ[u]   * 10.0f;
        float g     = gammap[u] * 10.0f;
        float tf = (float)t;
        // gamma_filter: t^n * exp(-t/tau) / tau^(n+1) / Gamma(n+1)
        float lt = (t == 0) ? 0.0f : __logf(tf);
        float kc = ((t == 0) ? 0.0f : __expf(n_c * lt - tf / tau_c))
                   * __expf(-(n_c + 1.0f) * __logf(tau_c) - lgammaf(n_c + 1.0f));
        if (t == 0) kc = 0.0f;
        float kz2 = ((t == 0) ? 0.0f : __expf(n_z * lt - tf / tau_z))
                   * __expf(-(n_z + 1.0f) * __logf(tau_z) - lgammaf(n_z + 1.0f));
        if (t == 0) kz2 = 0.0f;
        Kz[t][u] = g * kc + (1.0f - g) * kz2;
    }
    __syncthreads();

    if (tid < Uv) {
        int u = tid;
        float best = Kz[0][u];
        int bi = 0;
        for (int t = 1; t < Tv; ++t) {
            if (Kz[t][u] > best) { best = Kz[t][u]; bi = t; }  // first max wins
        }
        int ti = Tv - bi;                 // T - z_shift
        if (ti > Tv - 1) ti = Tv - 1;
        if (ti < 0) ti = 0;
        tidx[u] = ti;
        g_ab[u] = make_float2(alpha[u] * 100.0f, beta[u] * 10.0f);
    }
    __syncthreads();

    if (tid < Tv * Uv) {
        int s = tid / Uv;
        int u = tid % Uv;
        int ti = tidx[u];
        g_wt[s][u] = (s <= ti) ? Kz[ti - s][u] : 0.0f;
    }
}

// ---------------------------------------------------------------------------
// Main: one warp per batch row.
//   z[u] = dot(x[b,:], w[:,u]);  scale[u] = a[u]/(1 + b[u]*z[u])
//   out[b*512 + t*8 + u] = scale[u] * x[b,t]
// Packed butterfly reduce (9 SHFLs), 1 division/lane, contiguous 512B STG.128s.
// ---------------------------------------------------------------------------
__global__ __launch_bounds__(256) void main_kernel(const float* __restrict__ x,
                                                   float* __restrict__ out) {
    int warp = blockIdx.x * (blockDim.x >> 5) + (threadIdx.x >> 5);
    int lane = threadIdx.x & 31;

    // Load x[b, 2*lane], x[b, 2*lane+1]  (coalesced 256B per warp)
    const float2* xb = (const float2*)(x + (size_t)warp * Tv);
    float2 xv = xb[lane];

    // w rows 2*lane and 2*lane+1, all 8 channels: 4x LDG.128 (L1-resident)
    const float4* wp = (const float4*)g_wt;
    float4 w0a = wp[(2 * lane) * 2 + 0];
    float4 w0b = wp[(2 * lane) * 2 + 1];
    float4 w1a = wp[(2 * lane + 1) * 2 + 0];
    float4 w1b = wp[(2 * lane + 1) * 2 + 1];

    // Partial dot products for 8 channels
    float s[Uv];
    s[0] = fmaf(xv.x, w0a.x, xv.y * w1a.x);
    s[1] = fmaf(xv.x, w0a.y, xv.y * w1a.y);
    s[2] = fmaf(xv.x, w0a.z, xv.y * w1a.z);
    s[3] = fmaf(xv.x, w0a.w, xv.y * w1a.w);
    s[4] = fmaf(xv.x, w0b.x, xv.y * w1b.x);
    s[5] = fmaf(xv.x, w0b.y, xv.y * w1b.y);
    s[6] = fmaf(xv.x, w0b.z, xv.y * w1b.z);
    s[7] = fmaf(xv.x, w0b.w, xv.y * w1b.w);

    const unsigned FULL = 0xffffffffu;
    int b0 = lane & 1, b1 = (lane >> 1) & 1, b2 = (lane >> 2) & 1;

    // Level 1 (xor 1): halve channels 8->4.  Lane keeps channels 4*b0+j.
#pragma unroll
    for (int j = 0; j < 4; ++j) {
        float send = b0 ? s[j] : s[j + 4];
        float recv = __shfl_xor_sync(FULL, send, 1);
        float keep = b0 ? s[j + 4] : s[j];
        s[j] = keep + recv;
    }
    // Level 2 (xor 2): 4->2.  ch = 4*b0 + 2*b1 + j
#pragma unroll
    for (int j = 0; j < 2; ++j) {
        float send = b1 ? s[j] : s[j + 2];
        float recv = __shfl_xor_sync(FULL, send, 2);
        float keep = b1 ? s[j + 2] : s[j];
        s[j] = keep + recv;
    }
    // Level 3 (xor 4): 2->1.  ch = 4*b0 + 2*b1 + b2
    float z;
    {
        float send = b2 ? s[0] : s[1];
        float recv = __shfl_xor_sync(FULL, send, 4);
        float keep = b2 ? s[1] : s[0];
        z = keep + recv;
    }
    // Levels 4,5: plain reduce over remaining lane groups
    z += __shfl_xor_sync(FULL, z, 8);
    z += __shfl_xor_sync(FULL, z, 16);

    // This lane's channel and its scale (one division per lane)
    int u = 4 * b0 + 2 * b1 + b2;
    float2 ab = g_ab[u];
    float myscale = __fdividef(ab.x, fmaf(ab.y, z, 1.0f));

    // Gather the 4 channels this lane stores: u = (lane&1)*4 + j.
    // Lane holding channel u is src(u) = (u>>2) | (((u>>1)&1)<<1) | ((u&1)<<2).
    // With u = hi*4+j (j const): src = hi + 2*((j>>1)&1) + 4*(j&1).
    int hi = lane & 1;
    float c0 = __shfl_sync(FULL, myscale, hi + 0);      // j=0
    float c1 = __shfl_sync(FULL, myscale, hi + 4);      // j=1
    float c2 = __shfl_sync(FULL, myscale, hi + 2);      // j=2
    float c3 = __shfl_sync(FULL, myscale, hi + 6);      // j=3

    float* ob = out + (size_t)warp * (Tv * Uv);
    int src = lane >> 2;           // partial source-lane term
    int sel = (lane >> 1) & 1;     // which float2 component holds x[t]

#pragma unroll
    for (int i = 0; i < 4; ++i) {
        // Element index = i*128 + lane*4 + j  ->  t = i*16 + (lane>>1)
        // x[t] lives in lane (i*8 + (lane>>2)), component sel
        int slane = i * 8 + src;
        float xa  = __shfl_sync(FULL, xv.x, slane);
        float xb2 = __shfl_sync(FULL, xv.y, slane);
        float xt = sel ? xb2 : xa;
        float4 v = make_float4(c0 * xt, c1 * xt, c2 * xt, c3 * xt);
        *(float4*)(ob + i * 128 + lane * 4) = v;   // contiguous 512B per STG across warp
    }
}

extern "C" void kernel_launch(void* const* d_in, const int* in_sizes, int n_in,
                              void* d_out, int out_size) {
    // Input order: inputs, alpha, beta, gamma, zeta, tauY, nY, tauZ, nZ, tauC, nC
    const float* inputs = (const float*)d_in[0];
    const float* alpha  = (const float*)d_in[1];
    const float* beta   = (const float*)d_in[2];
    const float* gammap = (const float*)d_in[3];
    const float* tauZ   = (const float*)d_in[7];
    const float* nZ     = (const float*)d_in[8];
    const float* tauC   = (const float*)d_in[9];
    const float* nC     = (const float*)d_in[10];
    float* out = (float*)d_out;

    setup_kernel<<<1, 512>>>(alpha, beta, gammap, tauZ, nZ, tauC, nC);

    // One warp per batch: 65536 warps = 8192 blocks x 256 threads
    main_kernel<<<Bv / 8, 256>>>(inputs, out);
}

// round 8
// speedup vs baseline: 1.3129x; 1.3117x over previous
#include <cuda_runtime.h>
#include <math.h>

#define Bv 65536
#define Tv 64
#define Uv 8
#define NB 8   // batches per warp

// Precomputed state (written by setup kernel, read by main kernel).
__device__ float  g_wt[Tv][Uv];   // transposed flipped weights: w_t[s][u] = Kz[t_idx[u]-s, u] (0 if s>t_idx)
__device__ float2 g_ab[Uv];       // (alpha*100, beta*10)

// ---------------------------------------------------------------------------
// Setup: per-channel constants once, then Kz, argmax -> t_idx, flipped weights.
// ---------------------------------------------------------------------------
__global__ void setup_kernel(const float* __restrict__ alpha,
                             const float* __restrict__ beta,
                             const float* __restrict__ gammap,
                             const float* __restrict__ tauZ,
                             const float* __restrict__ nZ,
                             const float* __restrict__ tauC,
                             const float* __restrict__ nC) {
    __shared__ float Kz[Tv][Uv];
    __shared__ int   tidx[Uv];
    __shared__ float s_tc[Uv], s_nc[Uv], s_normc[Uv];
    __shared__ float s_tz[Uv], s_nz[Uv], s_normz[Uv];
    __shared__ float s_g[Uv];

    int tid = threadIdx.x;  // 512 threads

    // Phase 1: per-channel constants (8 threads)
    if (tid < Uv) {
        int u = tid;
        float tau_c = tauC[u] * 100.0f;
        float n_c   = nC[u]   * 10.0f;
        float tau_z = tauZ[u] * 100.0f;
        float n_z   = nZ[u]   * 10.0f;
        s_tc[u] = tau_c;  s_nc[u] = n_c;
        s_tz[u] = tau_z;  s_nz[u] = n_z;
        s_g[u]  = gammap[u] * 10.0f;
        // 1 / (tau^(n+1) * Gamma(n+1))
        s_normc[u] = __expf(-(n_c + 1.0f) * __logf(tau_c) - lgammaf(n_c + 1.0f));
        s_normz[u] = __expf(-(n_z + 1.0f) * __logf(tau_z) - lgammaf(n_z + 1.0f));
        g_ab[u] = make_float2(alpha[u] * 100.0f, beta[u] * 10.0f);
    }
    __syncthreads();

    // Phase 2: Kz[t][u]  (n>0 always, so t=0 -> 0)
    if (tid < Tv * Uv) {
        int t = tid / Uv;
        int u = tid % Uv;
        float tf = (float)t;
        float kc = 0.0f, kz2 = 0.0f;
        if (t > 0) {
            float lt = __logf(tf);
            kc  = __expf(s_nc[u] * lt - tf / s_tc[u]) * s_normc[u];
            kz2 = __expf(s_nz[u] * lt - tf / s_tz[u]) * s_normz[u];
        }
        float g = s_g[u];
        Kz[t][u] = g * kc + (1.0f - g) * kz2;
    }
    __syncthreads();

    // Phase 3: argmax -> t_idx
    if (tid < Uv) {
        int u = tid;
        float best = Kz[0][u];
        int bi = 0;
        for (int t = 1; t < Tv; ++t) {
            if (Kz[t][u] > best) { best = Kz[t][u]; bi = t; }  // first max wins
        }
        int ti = Tv - bi;                 // T - z_shift
        if (ti > Tv - 1) ti = Tv - 1;
        if (ti < 0) ti = 0;
        tidx[u] = ti;
    }
    __syncthreads();

    // Phase 4: flipped transposed weights
    if (tid < Tv * Uv) {
        int s = tid / Uv;
        int u = tid % Uv;
        int ti = tidx[u];
        g_wt[s][u] = (s <= ti) ? Kz[ti - s][u] : 0.0f;
    }
}

// ---------------------------------------------------------------------------
// Main: one warp per NB batch rows; weights resident in registers.
//   z[u] = dot(x[b,:], w[:,u]);  scale[u] = a[u]/(1 + b[u]*z[u])
//   out[b*512 + t*8 + u] = scale[u] * x[b,t]
// ---------------------------------------------------------------------------
__global__ __launch_bounds__(256) void main_kernel(const float* __restrict__ x,
                                                   float* __restrict__ out) {
    int warp = blockIdx.x * (blockDim.x >> 5) + (threadIdx.x >> 5);
    int lane = threadIdx.x & 31;
    const unsigned FULL = 0xffffffffu;

    // Persistent weights: rows 2*lane, 2*lane+1, all 8 channels (16 regs)
    const float4* wp = (const float4*)g_wt;
    float4 w0a = wp[(2 * lane) * 2 + 0];
    float4 w0b = wp[(2 * lane) * 2 + 1];
    float4 w1a = wp[(2 * lane + 1) * 2 + 0];
    float4 w1b = wp[(2 * lane + 1) * 2 + 1];

    int b0 = lane & 1, b1 = (lane >> 1) & 1, b2 = (lane >> 2) & 1;
    int u = 4 * b0 + 2 * b1 + b2;       // this lane's channel after packed reduce
    float2 ab = g_ab[u];

    int hi  = lane & 1;                  // channel group for stores
    int src = lane >> 2;                 // x-redistribution source term
    int sel = (lane >> 1) & 1;

    size_t base = (size_t)warp * NB;
    const float2* xb = (const float2*)(x + base * Tv);
    float* ob = out + base * (Tv * Uv);

#pragma unroll 4
    for (int n = 0; n < NB; ++n) {
        float2 xv = xb[n * 32 + lane];   // x[b, 2*lane], x[b, 2*lane+1]

        // Partial dot products, 8 channels
        float s[Uv];
        s[0] = fmaf(xv.x, w0a.x, xv.y * w1a.x);
        s[1] = fmaf(xv.x, w0a.y, xv.y * w1a.y);
        s[2] = fmaf(xv.x, w0a.z, xv.y * w1a.z);
        s[3] = fmaf(xv.x, w0a.w, xv.y * w1a.w);
        s[4] = fmaf(xv.x, w0b.x, xv.y * w1b.x);
        s[5] = fmaf(xv.x, w0b.y, xv.y * w1b.y);
        s[6] = fmaf(xv.x, w0b.z, xv.y * w1b.z);
        s[7] = fmaf(xv.x, w0b.w, xv.y * w1b.w);

        // Packed butterfly reduce: 9 SHFLs, lane ends with z for channel u
#pragma unroll
        for (int j = 0; j < 4; ++j) {
            float send = b0 ? s[j] : s[j + 4];
            float recv = __shfl_xor_sync(FULL, send, 1);
            float keep = b0 ? s[j + 4] : s[j];
            s[j] = keep + recv;
        }
#pragma unroll
        for (int j = 0; j < 2; ++j) {
            float send = b1 ? s[j] : s[j + 2];
            float recv = __shfl_xor_sync(FULL, send, 2);
            float keep = b1 ? s[j + 2] : s[j];
            s[j] = keep + recv;
        }
        float z;
        {
            float send = b2 ? s[0] : s[1];
            float recv = __shfl_xor_sync(FULL, send, 4);
            float keep = b2 ? s[1] : s[0];
            z = keep + recv;
        }
        z += __shfl_xor_sync(FULL, z, 8);
        z += __shfl_xor_sync(FULL, z, 16);

        // One division per lane
        float myscale = __fdividef(ab.x, fmaf(ab.y, z, 1.0f));

        // Gather the 4 channels this lane stores: u = hi*4 + j
        float c0 = __shfl_sync(FULL, myscale, hi + 0);   // j=0
        float c1 = __shfl_sync(FULL, myscale, hi + 4);   // j=1
        float c2 = __shfl_sync(FULL, myscale, hi + 2);   // j=2
        float c3 = __shfl_sync(FULL, myscale, hi + 6);   // j=3

        float* on = ob + n * (Tv * Uv);
#pragma unroll
        for (int i = 0; i < 4; ++i) {
            // Element = i*128 + lane*4 + j -> t = i*16 + (lane>>1)
            int slane = i * 8 + src;
            float xa  = __shfl_sync(FULL, xv.x, slane);
            float xb2 = __shfl_sync(FULL, xv.y, slane);
            float xt = sel ? xb2 : xa;
            float4 v = make_float4(c0 * xt, c1 * xt, c2 * xt, c3 * xt);
            // Streaming store (output is write-once, never re-read)
            __stcs((float4*)(on + i * 128 + lane * 4), v);
        }
    }
}

extern "C" void kernel_launch(void* const* d_in, const int* in_sizes, int n_in,
                              void* d_out, int out_size) {
    // Input order: inputs, alpha, beta, gamma, zeta, tauY, nY, tauZ, nZ, tauC, nC
    const float* inputs = (const float*)d_in[0];
    const float* alpha  = (const float*)d_in[1];
    const float* beta   = (const float*)d_in[2];
    const float* gammap = (const float*)d_in[3];
    const float* tauZ   = (const float*)d_in[7];
    const float* nZ     = (const float*)d_in[8];
    const float* tauC   = (const float*)d_in[9];
    const float* nC     = (const float*)d_in[10];
    float* out = (float*)d_out;

    setup_kernel<<<1, 512>>>(alpha, beta, gammap, tauZ, nZ, tauC, nC);

    // 65536 batches / (8 warps * NB per warp) = 1024 blocks
    main_kernel<<<Bv / (8 * NB), 256>>>(inputs, out);
}